// round 2
// baseline (speedup 1.0000x reference)
#include <cuda_runtime.h>
#include <math.h>

// Problem constants
#define BT    8       // B*T
#define NQ    1600    // H*W
#define NK    1600    // Hm*Wm
#define DQ    256     // QUERY_DIM
#define DK    128     // KEY_DIM
#define NHEAD 4
#define HD    32      // HEAD_DIM
#define INNER 128     // NHEAD*HD

// Scratch (device globals; allocation-free rule)
__device__ float g_Q[BT * NHEAD * NQ * HD];   // [bt][h][n][32]
__device__ float g_K[BT * NHEAD * NK * HD];
__device__ float g_V[BT * NHEAD * NK * HD];
__device__ float g_O[BT * NQ * INNER];        // [bt][n][128]

// ---------------------------------------------------------------------------
// Projection: Out[bt][h][n][dh] = scale * sum_d In[bt][d][n] * W[d][h*32+dh]
// In is [BT][Din][1600] (channel-major), W is [Din][128].
// Block: 64 n-rows x 128 i-cols, 256 threads, thread tile 4x8.
// ---------------------------------------------------------------------------
__global__ __launch_bounds__(256)
void proj_kernel(const float* __restrict__ In, const float* __restrict__ W,
                 float* __restrict__ Out, int Din, float scale) {
    const int bt = blockIdx.y;
    const int n0 = blockIdx.x * 64;
    const float* Ib = In + (size_t)bt * Din * NQ;

    __shared__ __align__(16) float a_s[16][68];    // [d][n]
    __shared__ __align__(16) float w_s[16][132];   // [d][i]

    const int tid = threadIdx.x;
    const int ty = tid >> 4, tx = tid & 15;

    float acc[4][8];
#pragma unroll
    for (int j = 0; j < 4; j++)
#pragma unroll
        for (int c = 0; c < 8; c++) acc[j][c] = 0.f;

    for (int d0 = 0; d0 < Din; d0 += 16) {
        __syncthreads();
        // load input chunk [16 d][64 n]
        {
            int d = tid >> 4;
            int n = (tid & 15) * 4;
            float4 v = *(const float4*)(Ib + (size_t)(d0 + d) * NQ + n0 + n);
            *(float4*)&a_s[d][n] = v;
        }
        // load weight chunk [16 d][128 i]
#pragma unroll
        for (int k = 0; k < 2; k++) {
            int idx4 = tid + k * 256;
            int d = idx4 >> 5;
            int i = (idx4 & 31) * 4;
            *(float4*)&w_s[d][i] = *(const float4*)(W + (size_t)(d0 + d) * 128 + i);
        }
        __syncthreads();

#pragma unroll
        for (int dd = 0; dd < 16; dd++) {
            float4 a  = *(const float4*)&a_s[dd][ty * 4];
            float4 b0 = *(const float4*)&w_s[dd][tx * 8];
            float4 b1 = *(const float4*)&w_s[dd][tx * 8 + 4];
            float av[4] = {a.x, a.y, a.z, a.w};
            float bv[8] = {b0.x, b0.y, b0.z, b0.w, b1.x, b1.y, b1.z, b1.w};
#pragma unroll
            for (int j = 0; j < 4; j++)
#pragma unroll
                for (int c = 0; c < 8; c++) acc[j][c] += av[j] * bv[c];
        }
    }

    // write: Out[((bt*4+h)*1600 + n)*32 + dh]
#pragma unroll
    for (int j = 0; j < 4; j++) {
        int n = n0 + ty * 4 + j;
#pragma unroll
        for (int cg = 0; cg < 2; cg++) {
            int i = tx * 8 + cg * 4;
            int h = i >> 5, dh = i & 31;
            float4 o = make_float4(acc[j][cg * 4 + 0] * scale, acc[j][cg * 4 + 1] * scale,
                                   acc[j][cg * 4 + 2] * scale, acc[j][cg * 4 + 3] * scale);
            *(float4*)&Out[(((size_t)bt * 4 + h) * NQ + n) * HD + dh] = o;
        }
    }
}

// ---------------------------------------------------------------------------
// Flash attention per (bt, h): QT=64 queries per block, KT=64 keys per tile,
// online softmax. Scale already folded into Q.
// ---------------------------------------------------------------------------
#define QT 64
#define KT 64

__global__ __launch_bounds__(256)
void attn_kernel(const float* __restrict__ Q, const float* __restrict__ K,
                 const float* __restrict__ V, float* __restrict__ O) {
    const int qt0 = blockIdx.x * QT;
    const int h = blockIdx.y;
    const int bt = blockIdx.z;
    const float* Qb = Q + (((size_t)bt * NHEAD + h) * NQ) * HD;
    const float* Kb = K + (((size_t)bt * NHEAD + h) * NK) * HD;
    const float* Vb = V + (((size_t)bt * NHEAD + h) * NK) * HD;

    __shared__ __align__(16) float qt_s[HD][68];   // [d][n] transposed Q tile
    __shared__ __align__(16) float kt_s[HD][68];   // [d][n] transposed K tile
    __shared__ __align__(16) float v_s[KT][36];    // [k][d] V tile
    __shared__ __align__(16) float p_s[KT][68];    // [k][r] transposed P tile

    const int tid = threadIdx.x;
    const int ty = tid >> 4, tx = tid & 15;
    const int r0 = ty * 4, c0 = tx * 4;
    const int dc = tx * 2;

    // load Q tile transposed
#pragma unroll
    for (int k = 0; k < 2; k++) {
        int idx4 = tid + k * 256;
        int n = idx4 >> 3;
        int d = (idx4 & 7) * 4;
        float4 v4 = *(const float4*)(Qb + (size_t)(qt0 + n) * HD + d);
        qt_s[d + 0][n] = v4.x; qt_s[d + 1][n] = v4.y;
        qt_s[d + 2][n] = v4.z; qt_s[d + 3][n] = v4.w;
    }

    float m[4], l[4], accO[4][2];
#pragma unroll
    for (int j = 0; j < 4; j++) {
        m[j] = -1e30f; l[j] = 0.f; accO[j][0] = 0.f; accO[j][1] = 0.f;
    }

    for (int kt0 = 0; kt0 < NK; kt0 += KT) {
        __syncthreads();  // protect kt_s/v_s/p_s from previous iteration readers
        // load K (transposed) and V (row-major) tiles
#pragma unroll
        for (int k = 0; k < 2; k++) {
            int idx4 = tid + k * 256;
            int n = idx4 >> 3;
            int d = (idx4 & 7) * 4;
            float4 kv = *(const float4*)(Kb + (size_t)(kt0 + n) * HD + d);
            kt_s[d + 0][n] = kv.x; kt_s[d + 1][n] = kv.y;
            kt_s[d + 2][n] = kv.z; kt_s[d + 3][n] = kv.w;
            float4 vv = *(const float4*)(Vb + (size_t)(kt0 + n) * HD + d);
            *(float4*)&v_s[n][d] = vv;
        }
        __syncthreads();

        // S = Q K^T  (scale folded into Q)
        float accS[4][4];
#pragma unroll
        for (int j = 0; j < 4; j++)
#pragma unroll
            for (int i = 0; i < 4; i++) accS[j][i] = 0.f;

#pragma unroll 8
        for (int d = 0; d < HD; d++) {
            float4 qa = *(const float4*)&qt_s[d][r0];
            float4 kb = *(const float4*)&kt_s[d][c0];
            accS[0][0] += qa.x * kb.x; accS[0][1] += qa.x * kb.y; accS[0][2] += qa.x * kb.z; accS[0][3] += qa.x * kb.w;
            accS[1][0] += qa.y * kb.x; accS[1][1] += qa.y * kb.y; accS[1][2] += qa.y * kb.z; accS[1][3] += qa.y * kb.w;
            accS[2][0] += qa.z * kb.x; accS[2][1] += qa.z * kb.y; accS[2][2] += qa.z * kb.z; accS[2][3] += qa.z * kb.w;
            accS[3][0] += qa.w * kb.x; accS[3][1] += qa.w * kb.y; accS[3][2] += qa.w * kb.z; accS[3][3] += qa.w * kb.w;
        }

        // online softmax (row groups of 16 tx lanes, xor-shfl within 16)
#pragma unroll
        for (int j = 0; j < 4; j++) {
            float mt = fmaxf(fmaxf(accS[j][0], accS[j][1]), fmaxf(accS[j][2], accS[j][3]));
#pragma unroll
            for (int off = 8; off > 0; off >>= 1)
                mt = fmaxf(mt, __shfl_xor_sync(0xffffffffu, mt, off));
            float mn = fmaxf(m[j], mt);
            float alpha = __expf(m[j] - mn);
            m[j] = mn;
            float ls = 0.f;
#pragma unroll
            for (int i = 0; i < 4; i++) {
                float p = __expf(accS[j][i] - mn);
                accS[j][i] = p;
                ls += p;
            }
#pragma unroll
            for (int off = 8; off > 0; off >>= 1)
                ls += __shfl_xor_sync(0xffffffffu, ls, off);
            l[j] = l[j] * alpha + ls;
            accO[j][0] *= alpha;
            accO[j][1] *= alpha;
        }

        // store P transposed: p_s[key][row]
#pragma unroll
        for (int i = 0; i < 4; i++) {
            float4 pv = make_float4(accS[0][i], accS[1][i], accS[2][i], accS[3][i]);
            *(float4*)&p_s[c0 + i][r0] = pv;
        }
        __syncthreads();

        // O += P @ V
#pragma unroll 8
        for (int k = 0; k < KT; k++) {
            float4 p4 = *(const float4*)&p_s[k][r0];
            float2 v2 = *(const float2*)&v_s[k][dc];
            accO[0][0] += p4.x * v2.x; accO[0][1] += p4.x * v2.y;
            accO[1][0] += p4.y * v2.x; accO[1][1] += p4.y * v2.y;
            accO[2][0] += p4.z * v2.x; accO[2][1] += p4.z * v2.y;
            accO[3][0] += p4.w * v2.x; accO[3][1] += p4.w * v2.y;
        }
    }

    // epilogue: normalize and write O[bt][n][h*32+dc]
#pragma unroll
    for (int j = 0; j < 4; j++) {
        float inv = 1.0f / l[j];
        int n = qt0 + r0 + j;
        float2 o2 = make_float2(accO[j][0] * inv, accO[j][1] * inv);
        *(float2*)&O[((size_t)bt * NQ + n) * INNER + h * HD + dc] = o2;
    }
}

// ---------------------------------------------------------------------------
// Output projection: out[bt][dout][n] = sum_i O[bt][n][i]*Wo[i][dout] + bo[dout]
// Block: 64 n x 128 dout, 256 threads, thread tile 4x8, smem transpose on out.
// ---------------------------------------------------------------------------
__global__ __launch_bounds__(256)
void outproj_kernel(const float* __restrict__ O, const float* __restrict__ Wo,
                    const float* __restrict__ bo, float* __restrict__ Out) {
    const int bt = blockIdx.z;
    const int n0 = blockIdx.x * 64;
    const int do0 = blockIdx.y * 128;

    __shared__ __align__(16) float o_s[16][68];    // [i][n]
    __shared__ __align__(16) float w_s[16][132];   // [i][dout]
    __shared__ __align__(16) float t_s[64][129];   // [n][dout] for transposed write

    const int tid = threadIdx.x;
    const int ty = tid >> 4, tx = tid & 15;

    float acc[4][8];
#pragma unroll
    for (int j = 0; j < 4; j++)
#pragma unroll
        for (int c = 0; c < 8; c++) acc[j][c] = 0.f;

    for (int i0 = 0; i0 < INNER; i0 += 16) {
        __syncthreads();
        // load O chunk [64 n][16 i] -> transpose into o_s[i][n]
        {
            int n = tid >> 2;
            int i = (tid & 3) * 4;
            float4 v = *(const float4*)(O + ((size_t)bt * NQ + n0 + n) * INNER + i0 + i);
            o_s[i + 0][n] = v.x; o_s[i + 1][n] = v.y;
            o_s[i + 2][n] = v.z; o_s[i + 3][n] = v.w;
        }
        // load Wo chunk [16 i][128 dout]
#pragma unroll
        for (int k = 0; k < 2; k++) {
            int idx4 = tid + k * 256;
            int i = idx4 >> 5;
            int d = (idx4 & 31) * 4;
            *(float4*)&w_s[i][d] = *(const float4*)(Wo + (size_t)(i0 + i) * DQ + do0 + d);
        }
        __syncthreads();

#pragma unroll
        for (int ii = 0; ii < 16; ii++) {
            float4 a  = *(const float4*)&o_s[ii][ty * 4];
            float4 b0 = *(const float4*)&w_s[ii][tx * 8];
            float4 b1 = *(const float4*)&w_s[ii][tx * 8 + 4];
            float av[4] = {a.x, a.y, a.z, a.w};
            float bv[8] = {b0.x, b0.y, b0.z, b0.w, b1.x, b1.y, b1.z, b1.w};
#pragma unroll
            for (int j = 0; j < 4; j++)
#pragma unroll
                for (int c = 0; c < 8; c++) acc[j][c] += av[j] * bv[c];
        }
    }

    __syncthreads();
    // add bias, stage into smem for coalesced transposed write
#pragma unroll
    for (int j = 0; j < 4; j++)
#pragma unroll
        for (int c = 0; c < 8; c++)
            t_s[ty * 4 + j][tx * 8 + c] = acc[j][c] + __ldg(&bo[do0 + tx * 8 + c]);
    __syncthreads();

    // t_s is [n][dout]; iterate so consecutive tid -> consecutive n (coalesced
    // global write), reading t_s[n][d] (row stride 129 -> conflict-free).
#pragma unroll
    for (int it = 0; it < 32; it++) {
        int idx = it * 256 + tid;
        int d = idx >> 6;      // dout offset 0..127
        int n = idx & 63;      // n offset 0..63
        Out[((size_t)bt * DQ + do0 + d) * NQ + n0 + n] = t_s[n][d];
    }
}

// ---------------------------------------------------------------------------
extern "C" void kernel_launch(void* const* d_in, const int* in_sizes, int n_in,
                              void* d_out, int out_size) {
    const float* query = (const float*)d_in[0];
    const float* key   = (const float*)d_in[1];
    const float* value = (const float*)d_in[2];
    const float* Wq    = (const float*)d_in[3];
    const float* Wk    = (const float*)d_in[4];
    const float* Wv    = (const float*)d_in[5];
    const float* Wo    = (const float*)d_in[6];
    const float* bo    = (const float*)d_in[7];
    float* out = (float*)d_out;

    float *gQ, *gK, *gV, *gO;
    cudaGetSymbolAddress((void**)&gQ, g_Q);
    cudaGetSymbolAddress((void**)&gK, g_K);
    cudaGetSymbolAddress((void**)&gV, g_V);
    cudaGetSymbolAddress((void**)&gO, g_O);

    dim3 blk(256);
    const float scale = 0.17677669529663687f;  // 1/sqrt(32)

    proj_kernel<<<dim3(NQ / 64, BT), blk>>>(query, Wq, gQ, DQ, scale);
    proj_kernel<<<dim3(NK / 64, BT), blk>>>(key,   Wk, gK, DK, 1.0f);
    proj_kernel<<<dim3(NK / 64, BT), blk>>>(value, Wv, gV, DK, 1.0f);
    attn_kernel<<<dim3(NQ / QT, NHEAD, BT), blk>>>(gQ, gK, gV, gO);
    outproj_kernel<<<dim3(NQ / 64, DQ / 128, BT), blk>>>(gO, Wo, bo, out);
}